// round 8
// baseline (speedup 1.0000x reference)
#include <cuda_runtime.h>

// Malvar-He-Cutler demosaic, GB300 (sm_103a). Round 8:
//  - R3 smem layout (left halo 2) so each window row is two ALIGNED LDS.128
//    (4 conflict-free phases) instead of R6/R7's 4-way-conflicted LDS.64:
//    LDS crossbar cycles halved (96 -> 48 per warp).
//  - one 2x4 quad per thread, single-pass 6-row basis accumulation (R7 math).
//  - coalesced float2 staging (R3-proven), float4 streaming stores.

#define TR 16
#define TC 128
#define SR (TR + 4)    // 20 staged rows
#define SC (TC + 8)    // 136 cols: global tile_c0-2 .. tile_c0+133

__device__ __forceinline__ float clip01(float v) {
    return fminf(fmaxf(v, 0.0f), 1.0f);
}
__device__ __forceinline__ int refl(int i, int n) {
    i = (i < 0) ? -i : i;
    return (i >= n) ? (2 * n - 2 - i) : i;
}

__global__ void __launch_bounds__(256, 4)
demosaic_kernel(const float* __restrict__ x, float* __restrict__ out,
                int H, int W)
{
    __shared__ __align__(16) float s[SR][SC];

    const int tid     = threadIdx.x;
    const int tile_c0 = blockIdx.x * TC;
    const int tile_r0 = blockIdx.y * TR;
    const int r0 = tile_r0 - 2;
    const int c0 = tile_c0 - 2;   // even -> 8B-aligned global base

    const bool interior = (r0 >= 0) & (r0 + SR <= H) & (c0 >= 0) & (c0 + SC <= W);

    if (interior) {
        const float2* __restrict__ xg =
            reinterpret_cast<const float2*>(x + (size_t)r0 * W + c0);
        const int wv = W >> 1;                 // row stride in float2
        #pragma unroll
        for (int k = 0; k < (SR * (SC / 2) + 255) / 256; ++k) {
            const int idx = tid + k * 256;
            if (idx < SR * (SC / 2)) {
                const int lr = idx / (SC / 2);
                const int lc = idx - lr * (SC / 2);
                *reinterpret_cast<float2*>(&s[lr][2 * lc]) = xg[(size_t)lr * wv + lc];
            }
        }
    } else {
        for (int idx = tid; idx < SR * SC; idx += 256) {
            const int lr = idx / SC;
            const int lc = idx - lr * SC;
            s[lr][lc] = x[(size_t)refl(r0 + lr, H) * W + refl(c0 + lc, W)];
        }
    }
    __syncthreads();

    // ---- Compute: one 2x4 quad per thread ----
    const int tx = tid & 31;          // col quad -> global cols tile_c0+4tx .. +3
    const int ty = tid >> 5;          // row pair -> global rows tile_r0+2ty .. +1
    const int sm_top = 2 * ty;        // smem row of window top (global row - 2)
    const int cb = 4 * tx;            // smem col of window left (global col - 2); 16B aligned

    // Vertical bases over 8 window cols.
    // Even out row: a=v0+v4, b=v1+v3, c=v2.  Odd out row: A=v1+v5, B=v2+v4, Cv=v3.
    float a[8], b[8], c[8], A[8], B[8], Cv[8];

    #pragma unroll
    for (int j = 0; j < 6; ++j) {
        const float4 u = *reinterpret_cast<const float4*>(&s[sm_top + j][cb]);
        const float4 v = *reinterpret_cast<const float4*>(&s[sm_top + j][cb + 4]);
        const float r[8] = {u.x, u.y, u.z, u.w, v.x, v.y, v.z, v.w};
        #pragma unroll
        for (int i = 0; i < 8; ++i) {
            if (j == 0)      { a[i] = r[i]; }
            else if (j == 1) { b[i] = r[i]; A[i] = r[i]; }
            else if (j == 2) { c[i] = r[i]; B[i] = r[i]; }
            else if (j == 3) { Cv[i] = r[i]; b[i] += r[i]; }
            else if (j == 4) { a[i] += r[i]; B[i] += r[i]; }
            else             { A[i] += r[i]; }
        }
    }

    const int gc  = tile_c0 + 4 * tx;
    const int gr0 = tile_r0 + 2 * ty;

    // ---- Row 0 (even global row): R Gr R Gr ----
    {
        float o[12];
        #pragma unroll
        for (int p = 0; p < 4; ++p) {
            const int q = p + 2;
            const float cc = c[q], bb = b[q], aa = a[q];
            const float s1 = c[q-1] + c[q+1];
            const float s2 = c[q-2] + c[q+2];
            const float s3 = b[q-1] + b[q+1];
            const float gi  = 0.125f * (4.0f*cc + 2.0f*(bb + s1) - (aa + s2));
            const float rgr = 0.125f * (5.0f*cc + 4.0f*s1 - s2 + 0.5f*aa - s3);
            const float rgv = 0.125f * (5.0f*cc + 4.0f*bb - aa + 0.5f*s2 - s3);
            const float rb  = 0.125f * (6.0f*cc + 2.0f*s3 - 1.5f*(aa + s2));
            if ((p & 1) == 0) { o[3*p]=clip01(cc);  o[3*p+1]=clip01(gi); o[3*p+2]=clip01(rb);  }
            else              { o[3*p]=clip01(rgr); o[3*p+1]=clip01(cc); o[3*p+2]=clip01(rgv); }
        }
        if (gr0 < H && gc + 4 <= W) {
            float4* d4 = reinterpret_cast<float4*>(out + ((size_t)gr0 * W + gc) * 3);
            __stcs(d4 + 0, make_float4(o[0], o[1], o[2],  o[3]));
            __stcs(d4 + 1, make_float4(o[4], o[5], o[6],  o[7]));
            __stcs(d4 + 2, make_float4(o[8], o[9], o[10], o[11]));
        } else if (gr0 < H) {
            #pragma unroll
            for (int p = 0; p < 4; ++p)
                if (gc + p < W) {
                    float* q2 = out + ((size_t)gr0 * W + gc + p) * 3;
                    q2[0] = o[3*p]; q2[1] = o[3*p+1]; q2[2] = o[3*p+2];
                }
        }
    }

    // ---- Row 1 (odd global row): Gb B Gb B ----
    {
        float o[12];
        #pragma unroll
        for (int p = 0; p < 4; ++p) {
            const int q = p + 2;
            const float cc = Cv[q], bb = B[q], aa = A[q];
            const float s1 = Cv[q-1] + Cv[q+1];
            const float s2 = Cv[q-2] + Cv[q+2];
            const float s3 = B[q-1] + B[q+1];
            const float gi  = 0.125f * (4.0f*cc + 2.0f*(bb + s1) - (aa + s2));
            const float rgr = 0.125f * (5.0f*cc + 4.0f*s1 - s2 + 0.5f*aa - s3);
            const float rgv = 0.125f * (5.0f*cc + 4.0f*bb - aa + 0.5f*s2 - s3);
            const float rb  = 0.125f * (6.0f*cc + 2.0f*s3 - 1.5f*(aa + s2));
            if ((p & 1) == 0) { o[3*p]=clip01(rgv); o[3*p+1]=clip01(cc); o[3*p+2]=clip01(rgr); }
            else              { o[3*p]=clip01(rb);  o[3*p+1]=clip01(gi); o[3*p+2]=clip01(cc);  }
        }
        const int gr1 = gr0 + 1;
        if (gr1 < H && gc + 4 <= W) {
            float4* d4 = reinterpret_cast<float4*>(out + ((size_t)gr1 * W + gc) * 3);
            __stcs(d4 + 0, make_float4(o[0], o[1], o[2],  o[3]));
            __stcs(d4 + 1, make_float4(o[4], o[5], o[6],  o[7]));
            __stcs(d4 + 2, make_float4(o[8], o[9], o[10], o[11]));
        } else if (gr1 < H) {
            #pragma unroll
            for (int p = 0; p < 4; ++p)
                if (gc + p < W) {
                    float* q2 = out + ((size_t)gr1 * W + gc + p) * 3;
                    q2[0] = o[3*p]; q2[1] = o[3*p+1]; q2[2] = o[3*p+2];
                }
        }
    }
}

extern "C" void kernel_launch(void* const* d_in, const int* in_sizes, int n_in,
                              void* d_out, int out_size)
{
    const float* x = (const float*)d_in[0];
    long nx = in_sizes[0];
    if (n_in > 1 && in_sizes[1] > in_sizes[0]) {  // defensive: pick the big tensor as x
        x = (const float*)d_in[1];
        nx = in_sizes[1];
    }

    const int W = 6144;
    const int H = (int)(nx / W);

    dim3 block(256);
    dim3 grid((unsigned)((W + TC - 1) / TC), (unsigned)((H + TR - 1) / TR));

    demosaic_kernel<<<grid, block>>>(x, (float*)d_out, H, W);
}

// round 9
// speedup vs baseline: 1.1535x; 1.1535x over previous
#include <cuda_runtime.h>

// Malvar-He-Cutler demosaic, GB300 (sm_103a). Round 9: NO shared memory.
// Direct global loads (3 aligned LDG.128 per row, 6 rows), accumulated on the
// fly into the 48-float vertical-basis set (R6/R7-proven ~48-reg structure),
// outputs streamed row-at-a-time. No barrier, no LDS -> no convoying; 18
// independent LDGs per thread for MLP. Vertical 3x row reuse lands in L2.

__device__ __forceinline__ float clip01(float v) {
    return fminf(fmaxf(v, 0.0f), 1.0f);
}
__device__ __forceinline__ int refl(int i, int n) {
    i = (i < 0) ? -i : i;
    return (i >= n) ? (2 * n - 2 - i) : i;
}

__global__ void __launch_bounds__(256, 3)
demosaic_kernel(const float* __restrict__ x, float* __restrict__ out,
                int H, int W)
{
    const int tx = threadIdx.x;                    // 0..31: col quad within block
    const int ty = threadIdx.y;                    // 0..7 : row pair within block
    const int base_c = (blockIdx.x * 32 + tx) * 4; // first output col (mult of 4)
    const int gr0    = (blockIdx.y * 8 + ty) * 2;  // first output row (even)
    if (base_c >= W || gr0 >= H) return;

    const bool fast = (gr0 >= 2) & (gr0 + 3 < H) & (base_c >= 4) & (base_c + 8 <= W);

    // Vertical bases over the 8 window cols [base_c-2, base_c+6).
    // Even out row: a=v0+v4, b=v1+v3, c=v2.  Odd out row: A=v1+v5, B=v2+v4, Cv=v3.
    float a[8], b[8], c[8], A[8], B[8], Cv[8];

    if (fast) {
        const float* rp = x + (size_t)(gr0 - 2) * W + (base_c - 4);
        #pragma unroll
        for (int j = 0; j < 6; ++j) {
            const float4 u = *reinterpret_cast<const float4*>(rp);
            const float4 v = *reinterpret_cast<const float4*>(rp + 4);
            const float4 w = *reinterpret_cast<const float4*>(rp + 8);
            rp += W;
            // window col i (0..7) = loaded float index i+2
            const float r[8] = {u.z, u.w, v.x, v.y, v.z, v.w, w.x, w.y};
            #pragma unroll
            for (int i = 0; i < 8; ++i) {
                if (j == 0)      { a[i] = r[i]; }
                else if (j == 1) { b[i] = r[i]; A[i] = r[i]; }
                else if (j == 2) { c[i] = r[i]; B[i] = r[i]; }
                else if (j == 3) { Cv[i] = r[i]; b[i] += r[i]; }
                else if (j == 4) { a[i] += r[i]; B[i] += r[i]; }
                else             { A[i] += r[i]; }
            }
        }
    } else {
        #pragma unroll
        for (int j = 0; j < 6; ++j) {
            const float* rp = x + (size_t)refl(gr0 - 2 + j, H) * W;
            float r[8];
            #pragma unroll
            for (int i = 0; i < 8; ++i)
                r[i] = rp[refl(base_c - 2 + i, W)];
            #pragma unroll
            for (int i = 0; i < 8; ++i) {
                if (j == 0)      { a[i] = r[i]; }
                else if (j == 1) { b[i] = r[i]; A[i] = r[i]; }
                else if (j == 2) { c[i] = r[i]; B[i] = r[i]; }
                else if (j == 3) { Cv[i] = r[i]; b[i] += r[i]; }
                else if (j == 4) { a[i] += r[i]; B[i] += r[i]; }
                else             { A[i] += r[i]; }
            }
        }
    }

    // ---- Row 0 (even global row): R Gr R Gr ----
    {
        float o[12];
        #pragma unroll
        for (int p = 0; p < 4; ++p) {
            const int q = p + 2;
            const float cc = c[q], bb = b[q], aa = a[q];
            const float s1 = c[q-1] + c[q+1];
            const float s2 = c[q-2] + c[q+2];
            const float s3 = b[q-1] + b[q+1];
            const float gi  = 0.125f * (4.0f*cc + 2.0f*(bb + s1) - (aa + s2));
            const float rgr = 0.125f * (5.0f*cc + 4.0f*s1 - s2 + 0.5f*aa - s3);
            const float rgv = 0.125f * (5.0f*cc + 4.0f*bb - aa + 0.5f*s2 - s3);
            const float rb  = 0.125f * (6.0f*cc + 2.0f*s3 - 1.5f*(aa + s2));
            if ((p & 1) == 0) { o[3*p]=clip01(cc);  o[3*p+1]=clip01(gi); o[3*p+2]=clip01(rb);  }
            else              { o[3*p]=clip01(rgr); o[3*p+1]=clip01(cc); o[3*p+2]=clip01(rgv); }
        }
        if (base_c + 4 <= W) {
            float4* d4 = reinterpret_cast<float4*>(out + ((size_t)gr0 * W + base_c) * 3);
            __stcs(d4 + 0, make_float4(o[0], o[1], o[2],  o[3]));
            __stcs(d4 + 1, make_float4(o[4], o[5], o[6],  o[7]));
            __stcs(d4 + 2, make_float4(o[8], o[9], o[10], o[11]));
        } else {
            #pragma unroll
            for (int p = 0; p < 4; ++p)
                if (base_c + p < W) {
                    float* q2 = out + ((size_t)gr0 * W + base_c + p) * 3;
                    q2[0] = o[3*p]; q2[1] = o[3*p+1]; q2[2] = o[3*p+2];
                }
        }
    }

    // ---- Row 1 (odd global row): Gb B Gb B ----
    {
        float o[12];
        #pragma unroll
        for (int p = 0; p < 4; ++p) {
            const int q = p + 2;
            const float cc = Cv[q], bb = B[q], aa = A[q];
            const float s1 = Cv[q-1] + Cv[q+1];
            const float s2 = Cv[q-2] + Cv[q+2];
            const float s3 = B[q-1] + B[q+1];
            const float gi  = 0.125f * (4.0f*cc + 2.0f*(bb + s1) - (aa + s2));
            const float rgr = 0.125f * (5.0f*cc + 4.0f*s1 - s2 + 0.5f*aa - s3);
            const float rgv = 0.125f * (5.0f*cc + 4.0f*bb - aa + 0.5f*s2 - s3);
            const float rb  = 0.125f * (6.0f*cc + 2.0f*s3 - 1.5f*(aa + s2));
            if ((p & 1) == 0) { o[3*p]=clip01(rgv); o[3*p+1]=clip01(cc); o[3*p+2]=clip01(rgr); }
            else              { o[3*p]=clip01(rb);  o[3*p+1]=clip01(gi); o[3*p+2]=clip01(cc);  }
        }
        const int gr1 = gr0 + 1;
        if (gr1 < H) {
            if (base_c + 4 <= W) {
                float4* d4 = reinterpret_cast<float4*>(out + ((size_t)gr1 * W + base_c) * 3);
                __stcs(d4 + 0, make_float4(o[0], o[1], o[2],  o[3]));
                __stcs(d4 + 1, make_float4(o[4], o[5], o[6],  o[7]));
                __stcs(d4 + 2, make_float4(o[8], o[9], o[10], o[11]));
            } else {
                #pragma unroll
                for (int p = 0; p < 4; ++p)
                    if (base_c + p < W) {
                        float* q2 = out + ((size_t)gr1 * W + base_c + p) * 3;
                        q2[0] = o[3*p]; q2[1] = o[3*p+1]; q2[2] = o[3*p+2];
                    }
            }
        }
    }
}

extern "C" void kernel_launch(void* const* d_in, const int* in_sizes, int n_in,
                              void* d_out, int out_size)
{
    const float* x = (const float*)d_in[0];
    long nx = in_sizes[0];
    if (n_in > 1 && in_sizes[1] > in_sizes[0]) {  // defensive: pick the big tensor as x
        x = (const float*)d_in[1];
        nx = in_sizes[1];
    }

    const int W = 6144;
    const int H = (int)(nx / W);

    dim3 block(32, 8);                         // 128 cols x 16 rows per block
    dim3 grid((unsigned)((W + 127) / 128),
              (unsigned)((H + 15) / 16));

    demosaic_kernel<<<grid, block>>>(x, (float*)d_out, H, W);
}